// round 1
// baseline (speedup 1.0000x reference)
#include <cuda_runtime.h>
#include <math.h>

#define NN 50000
#define NE 800000
#define DD 128
#define ED 16

// Scratch (allocation-free rule: __device__ globals)
__device__ float g_bufA[NN * DD];
__device__ float g_bufB[NN * DD];
__device__ int   g_idx64;

// ---------------------------------------------------------------------------
// Detect whether edge_idx is int64 or int32 (JAX may silently downcast).
// If the buffer really holds int64 node ids, every value is in [0, NN).
// If it holds int32 ids reinterpreted as int64, pairs combine to huge values.
// ---------------------------------------------------------------------------
__global__ void detect_idx_kernel(const long long* __restrict__ idx) {
    if (threadIdx.x == 0 && blockIdx.x == 0) {
        int ok = 1;
        #pragma unroll 1
        for (int i = 0; i < 64; i++) {
            long long v = idx[i];
            if (v < 0 || v >= (long long)NN) { ok = 0; break; }
        }
        g_idx64 = ok;
    }
}

// ---------------------------------------------------------------------------
// aggr = (1 + eps[l]) * xin
// ---------------------------------------------------------------------------
__global__ void init_aggr_kernel(const float* __restrict__ xin,
                                 const float* __restrict__ eps, int l,
                                 float* __restrict__ out) {
    float s = 1.0f + eps[l];
    const float4* x4 = (const float4*)xin;
    float4* o4 = (float4*)out;
    int total = NN * DD / 4;
    for (int i = blockIdx.x * blockDim.x + threadIdx.x; i < total;
         i += gridDim.x * blockDim.x) {
        float4 v = x4[i];
        o4[i] = make_float4(v.x * s, v.y * s, v.z * s, v.w * s);
    }
}

// ---------------------------------------------------------------------------
// Fused edge phase: e = edge_attr @ We + be ; msg = relu(x[src] + e) ;
// atomic scatter-add msg into aggr[dst].
// One warp per edge (grid-stride). Each lane owns 4 output dims (float4).
// We (16x128) cached in shared memory per block.
// ---------------------------------------------------------------------------
__global__ void edge_kernel(const float* __restrict__ xin,
                            const float* __restrict__ edge_attr,
                            const float* __restrict__ We,
                            const float* __restrict__ be,
                            const void* __restrict__ edge_idx,
                            float* __restrict__ aggr) {
    __shared__ float sWe[ED * DD];
    __shared__ float sbe[DD];
    for (int i = threadIdx.x; i < ED * DD; i += blockDim.x) sWe[i] = We[i];
    if (threadIdx.x < DD) sbe[threadIdx.x] = be[threadIdx.x];
    __syncthreads();

    const int is64 = g_idx64;
    const long long* idx64 = (const long long*)edge_idx;
    const int* idx32 = (const int*)edge_idx;

    int lane = threadIdx.x & 31;
    int warp = (blockIdx.x * blockDim.x + threadIdx.x) >> 5;
    int nwarps = (gridDim.x * blockDim.x) >> 5;
    int c0 = lane * 4;

    for (int e = warp; e < NE; e += nwarps) {
        // edge_attr row (16 floats), broadcast across the warp
        const float4* ea4 = (const float4*)(edge_attr + (size_t)e * ED);
        float4 e0 = ea4[0], e1 = ea4[1], e2 = ea4[2], e3 = ea4[3];
        float ea[16] = {e0.x, e0.y, e0.z, e0.w, e1.x, e1.y, e1.z, e1.w,
                        e2.x, e2.y, e2.z, e2.w, e3.x, e3.y, e3.z, e3.w};

        float4 acc = make_float4(sbe[c0], sbe[c0 + 1], sbe[c0 + 2], sbe[c0 + 3]);
        #pragma unroll
        for (int k = 0; k < ED; k++) {
            float4 w = ((const float4*)(sWe + k * DD))[lane];
            acc.x += ea[k] * w.x;
            acc.y += ea[k] * w.y;
            acc.z += ea[k] * w.z;
            acc.w += ea[k] * w.w;
        }

        long long src, dst;
        if (is64) {
            src = idx64[e];
            dst = idx64[NE + e];
        } else {
            src = idx32[e];
            dst = idx32[NE + e];
        }

        float4 xv = *(const float4*)(xin + (size_t)src * DD + c0);
        acc.x = fmaxf(acc.x + xv.x, 0.0f);
        acc.y = fmaxf(acc.y + xv.y, 0.0f);
        acc.z = fmaxf(acc.z + xv.z, 0.0f);
        acc.w = fmaxf(acc.w + xv.w, 0.0f);

        // sm_90+ vectorized float4 atomic add (one RED per 16B)
        atomicAdd((float4*)(aggr + (size_t)dst * DD + c0), acc);
    }
}

// ---------------------------------------------------------------------------
// Fused node MLP: C = gelu_exact(A @ W1 + b1) @ W2 + b2
// Block = 256 threads, tile = 128 rows. Both 128x128 weights + A tile (padded)
// in dynamic shared memory. 8x8 register tiles per thread.
// In-place safe (block reads its rows into SMEM before writing C).
// ---------------------------------------------------------------------------
#define SA_PITCH 132
#define MLP_SMEM_FLOATS (128 * SA_PITCH + 2 * 128 * 128 + 256)
#define MLP_SMEM_BYTES (MLP_SMEM_FLOATS * 4)

__global__ void mlp_kernel(const float* __restrict__ A,
                           const float* __restrict__ W1g,
                           const float* __restrict__ b1g,
                           const float* __restrict__ W2g,
                           const float* __restrict__ b2g,
                           float* __restrict__ C) {
    extern __shared__ float sm[];
    float* sA  = sm;                      // 128 x 132 (padded)
    float* sW1 = sm + 128 * SA_PITCH;     // 128 x 128
    float* sW2 = sW1 + 128 * 128;         // 128 x 128
    float* sb1 = sW2 + 128 * 128;         // 128
    float* sb2 = sb1 + 128;               // 128

    int tid = threadIdx.x;
    int row0 = blockIdx.x * 128;

    for (int i = tid; i < 128 * 32; i += 256) {
        ((float4*)sW1)[i] = ((const float4*)W1g)[i];
        ((float4*)sW2)[i] = ((const float4*)W2g)[i];
    }
    if (tid < 128) { sb1[tid] = b1g[tid]; sb2[tid] = b2g[tid]; }
    for (int i = tid; i < 128 * 32; i += 256) {
        int r = i >> 5, k4 = i & 31;
        int gr = row0 + r;
        float4 v = (gr < NN) ? ((const float4*)(A + (size_t)gr * DD))[k4]
                             : make_float4(0.f, 0.f, 0.f, 0.f);
        *(float4*)(sA + r * SA_PITCH + k4 * 4) = v;
    }
    __syncthreads();

    int tx = tid & 15, ty = tid >> 4;
    int r0 = ty * 8, cc = tx * 8;

    float acc[8][8];
    #pragma unroll
    for (int i = 0; i < 8; i++)
        #pragma unroll
        for (int j = 0; j < 8; j++) acc[i][j] = 0.0f;

    // GEMM1: acc = A @ W1
    #pragma unroll 4
    for (int k = 0; k < 128; k++) {
        float4 wa = *(const float4*)(sW1 + k * 128 + cc);
        float4 wb = *(const float4*)(sW1 + k * 128 + cc + 4);
        float a[8];
        #pragma unroll
        for (int i = 0; i < 8; i++) a[i] = sA[(r0 + i) * SA_PITCH + k];
        #pragma unroll
        for (int i = 0; i < 8; i++) {
            acc[i][0] += a[i] * wa.x; acc[i][1] += a[i] * wa.y;
            acc[i][2] += a[i] * wa.z; acc[i][3] += a[i] * wa.w;
            acc[i][4] += a[i] * wb.x; acc[i][5] += a[i] * wb.y;
            acc[i][6] += a[i] * wb.z; acc[i][7] += a[i] * wb.w;
        }
    }
    __syncthreads();  // everyone done reading sA before overwrite

    // bias + exact GELU, write H back into sA; reset accumulators
    #pragma unroll
    for (int i = 0; i < 8; i++) {
        #pragma unroll
        for (int j = 0; j < 8; j++) {
            float h = acc[i][j] + sb1[cc + j];
            h = 0.5f * h * (1.0f + erff(h * 0.70710678118654752f));
            sA[(r0 + i) * SA_PITCH + cc + j] = h;
            acc[i][j] = 0.0f;
        }
    }
    __syncthreads();

    // GEMM2: acc = H @ W2
    #pragma unroll 4
    for (int k = 0; k < 128; k++) {
        float4 wa = *(const float4*)(sW2 + k * 128 + cc);
        float4 wb = *(const float4*)(sW2 + k * 128 + cc + 4);
        float a[8];
        #pragma unroll
        for (int i = 0; i < 8; i++) a[i] = sA[(r0 + i) * SA_PITCH + k];
        #pragma unroll
        for (int i = 0; i < 8; i++) {
            acc[i][0] += a[i] * wa.x; acc[i][1] += a[i] * wa.y;
            acc[i][2] += a[i] * wa.z; acc[i][3] += a[i] * wa.w;
            acc[i][4] += a[i] * wb.x; acc[i][5] += a[i] * wb.y;
            acc[i][6] += a[i] * wb.z; acc[i][7] += a[i] * wb.w;
        }
    }

    // bias + store
    #pragma unroll
    for (int i = 0; i < 8; i++) {
        int gr = row0 + r0 + i;
        if (gr < NN) {
            float4 o0 = make_float4(acc[i][0] + sb2[cc],     acc[i][1] + sb2[cc + 1],
                                    acc[i][2] + sb2[cc + 2], acc[i][3] + sb2[cc + 3]);
            float4 o1 = make_float4(acc[i][4] + sb2[cc + 4], acc[i][5] + sb2[cc + 5],
                                    acc[i][6] + sb2[cc + 6], acc[i][7] + sb2[cc + 7]);
            *(float4*)(C + (size_t)gr * DD + cc) = o0;
            *(float4*)(C + (size_t)gr * DD + cc + 4) = o1;
        }
    }
}

// ---------------------------------------------------------------------------
// Launch
// ---------------------------------------------------------------------------
extern "C" void kernel_launch(void* const* d_in, const int* in_sizes, int n_in,
                              void* d_out, int out_size) {
    const float* x         = (const float*)d_in[0];
    const float* edge_attr = (const float*)d_in[1];
    const float* W1        = (const float*)d_in[2];
    const float* b1        = (const float*)d_in[3];
    const float* W2        = (const float*)d_in[4];
    const float* b2        = (const float*)d_in[5];
    const float* We        = (const float*)d_in[6];
    const float* be        = (const float*)d_in[7];
    const float* eps       = (const float*)d_in[8];
    const void*  edge_idx  = d_in[9];
    float* out = (float*)d_out;

    float *bufA, *bufB;
    cudaGetSymbolAddress((void**)&bufA, g_bufA);
    cudaGetSymbolAddress((void**)&bufB, g_bufB);

    cudaFuncSetAttribute(mlp_kernel,
                         cudaFuncAttributeMaxDynamicSharedMemorySize,
                         MLP_SMEM_BYTES);

    detect_idx_kernel<<<1, 32>>>((const long long*)edge_idx);

    const int mlp_blocks = (NN + 127) / 128;  // 391
    const float* xin = x;
    for (int l = 0; l < 3; l++) {
        float* aggr = (l == 1) ? bufB : bufA;
        float* xout = (l == 0) ? bufA : ((l == 1) ? bufB : out);

        init_aggr_kernel<<<256, 256>>>(xin, eps, l, aggr);
        edge_kernel<<<2048, 256>>>(xin, edge_attr, We + l * ED * DD,
                                   be + l * DD, edge_idx, aggr);
        mlp_kernel<<<mlp_blocks, 256, MLP_SMEM_BYTES>>>(
            aggr, W1 + l * DD * DD, b1 + l * DD,
            W2 + l * DD * DD, b2 + l * DD, xout);
        xin = xout;
    }
}

// round 2
// speedup vs baseline: 1.4152x; 1.4152x over previous
#include <cuda_runtime.h>
#include <math.h>

#define NN 50000
#define NE 800000
#define DD 128
#define ED 16

// Scratch (allocation-free rule: __device__ globals)
__device__ float g_bufA[NN * DD];
__device__ float g_bufB[NN * DD];
__device__ int   g_idx64;
__device__ int   g_cnt[NN];
__device__ int   g_rowptr[NN + 1];
__device__ int   g_cursor[NN];
__device__ int2  g_edges[NE];   // {src, edge_id} sorted by dst

// ---------------------------------------------------------------------------
// Detect whether edge_idx is int64 or int32 (JAX may silently downcast).
// ---------------------------------------------------------------------------
__global__ void detect_idx_kernel(const long long* __restrict__ idx) {
    if (threadIdx.x == 0 && blockIdx.x == 0) {
        int ok = 1;
        #pragma unroll 1
        for (int i = 0; i < 64; i++) {
            long long v = idx[i];
            if (v < 0 || v >= (long long)NN) { ok = 0; break; }
        }
        g_idx64 = ok;
    }
}

// ---------------------------------------------------------------------------
// CSR build: zero counts -> histogram over dst -> exclusive scan -> scatter
// ---------------------------------------------------------------------------
__global__ void zero_cnt_kernel() {
    int i = blockIdx.x * blockDim.x + threadIdx.x;
    if (i < NN) g_cnt[i] = 0;
}

__global__ void hist_kernel(const void* __restrict__ edge_idx) {
    int e = blockIdx.x * blockDim.x + threadIdx.x;
    if (e >= NE) return;
    int dst;
    if (g_idx64) dst = (int)((const long long*)edge_idx)[NE + e];
    else         dst = ((const int*)edge_idx)[NE + e];
    atomicAdd(&g_cnt[dst], 1);
}

__global__ void scan_kernel() {
    __shared__ int sdata[1024];
    __shared__ int running;
    if (threadIdx.x == 0) running = 0;
    __syncthreads();
    for (int base = 0; base < NN; base += 1024) {
        int i = base + threadIdx.x;
        int v = (i < NN) ? g_cnt[i] : 0;
        sdata[threadIdx.x] = v;
        __syncthreads();
        #pragma unroll
        for (int off = 1; off < 1024; off <<= 1) {
            int t = (threadIdx.x >= off) ? sdata[threadIdx.x - off] : 0;
            __syncthreads();
            sdata[threadIdx.x] += t;
            __syncthreads();
        }
        int excl = running + sdata[threadIdx.x] - v;
        if (i < NN) { g_rowptr[i] = excl; g_cursor[i] = excl; }
        __syncthreads();
        if (threadIdx.x == 1023) running += sdata[1023];
        __syncthreads();
    }
    if (threadIdx.x == 0) g_rowptr[NN] = running;
}

__global__ void scatter_kernel(const void* __restrict__ edge_idx) {
    int e = blockIdx.x * blockDim.x + threadIdx.x;
    if (e >= NE) return;
    int src, dst;
    if (g_idx64) {
        src = (int)((const long long*)edge_idx)[e];
        dst = (int)((const long long*)edge_idx)[NE + e];
    } else {
        src = ((const int*)edge_idx)[e];
        dst = ((const int*)edge_idx)[NE + e];
    }
    int pos = atomicAdd(&g_cursor[dst], 1);
    g_edges[pos] = make_int2(src, e);
}

// ---------------------------------------------------------------------------
// Edge aggregation (CSR, no atomics): one warp per dst node.
// Lane owns 4 feature cols. We (16x128) held in 64 registers per lane.
// aggr[d] = (1+eps)*x[d] + sum_{edges->d} relu(x[src] + edge_attr[e] @ We + be)
// ---------------------------------------------------------------------------
__global__ void __launch_bounds__(256)
aggr_kernel(const float* __restrict__ xin,
            const float* __restrict__ edge_attr,
            const float* __restrict__ We,
            const float* __restrict__ be,
            const float* __restrict__ eps, int l,
            float* __restrict__ aggr) {
    int lane = threadIdx.x & 31;
    int warp = (blockIdx.x * blockDim.x + threadIdx.x) >> 5;
    int nwarps = (gridDim.x * blockDim.x) >> 5;
    int c0 = lane * 4;

    float4 w[ED];
    #pragma unroll
    for (int k = 0; k < ED; k++)
        w[k] = *(const float4*)(We + k * DD + c0);
    float4 bias = *(const float4*)(be + c0);
    float s = 1.0f + eps[l];

    for (int d = warp; d < NN; d += nwarps) {
        float4 xv = *(const float4*)(xin + (size_t)d * DD + c0);
        float4 acc = make_float4(xv.x * s, xv.y * s, xv.z * s, xv.w * s);
        int beg = g_rowptr[d], end = g_rowptr[d + 1];
        for (int j = beg; j < end; j++) {
            int2 ed = g_edges[j];
            const float4* ea4 = (const float4*)(edge_attr + (size_t)ed.y * ED);
            float4 t0 = ea4[0], t1 = ea4[1], t2 = ea4[2], t3 = ea4[3];
            float ea[16] = {t0.x, t0.y, t0.z, t0.w, t1.x, t1.y, t1.z, t1.w,
                            t2.x, t2.y, t2.z, t2.w, t3.x, t3.y, t3.z, t3.w};
            float4 m = bias;
            #pragma unroll
            for (int k = 0; k < ED; k++) {
                m.x += ea[k] * w[k].x;
                m.y += ea[k] * w[k].y;
                m.z += ea[k] * w[k].z;
                m.w += ea[k] * w[k].w;
            }
            float4 xs = *(const float4*)(xin + (size_t)ed.x * DD + c0);
            acc.x += fmaxf(m.x + xs.x, 0.0f);
            acc.y += fmaxf(m.y + xs.y, 0.0f);
            acc.z += fmaxf(m.z + xs.z, 0.0f);
            acc.w += fmaxf(m.w + xs.w, 0.0f);
        }
        *(float4*)(aggr + (size_t)d * DD + c0) = acc;
    }
}

// ---------------------------------------------------------------------------
// Fused node MLP: C = gelu_exact(A @ W1 + b1) @ W2 + b2
// ---------------------------------------------------------------------------
#define SA_PITCH 132
#define MLP_SMEM_FLOATS (128 * SA_PITCH + 2 * 128 * 128 + 256)
#define MLP_SMEM_BYTES (MLP_SMEM_FLOATS * 4)

__global__ void mlp_kernel(const float* __restrict__ A,
                           const float* __restrict__ W1g,
                           const float* __restrict__ b1g,
                           const float* __restrict__ W2g,
                           const float* __restrict__ b2g,
                           float* __restrict__ C) {
    extern __shared__ float sm[];
    float* sA  = sm;                      // 128 x 132 (padded)
    float* sW1 = sm + 128 * SA_PITCH;     // 128 x 128
    float* sW2 = sW1 + 128 * 128;         // 128 x 128
    float* sb1 = sW2 + 128 * 128;         // 128
    float* sb2 = sb1 + 128;               // 128

    int tid = threadIdx.x;
    int row0 = blockIdx.x * 128;

    for (int i = tid; i < 128 * 32; i += 256) {
        ((float4*)sW1)[i] = ((const float4*)W1g)[i];
        ((float4*)sW2)[i] = ((const float4*)W2g)[i];
    }
    if (tid < 128) { sb1[tid] = b1g[tid]; sb2[tid] = b2g[tid]; }
    for (int i = tid; i < 128 * 32; i += 256) {
        int r = i >> 5, k4 = i & 31;
        int gr = row0 + r;
        float4 v = (gr < NN) ? ((const float4*)(A + (size_t)gr * DD))[k4]
                             : make_float4(0.f, 0.f, 0.f, 0.f);
        *(float4*)(sA + r * SA_PITCH + k4 * 4) = v;
    }
    __syncthreads();

    int tx = tid & 15, ty = tid >> 4;
    int r0 = ty * 8, cc = tx * 8;

    float acc[8][8];
    #pragma unroll
    for (int i = 0; i < 8; i++)
        #pragma unroll
        for (int j = 0; j < 8; j++) acc[i][j] = 0.0f;

    #pragma unroll 4
    for (int k = 0; k < 128; k++) {
        float4 wa = *(const float4*)(sW1 + k * 128 + cc);
        float4 wb = *(const float4*)(sW1 + k * 128 + cc + 4);
        float a[8];
        #pragma unroll
        for (int i = 0; i < 8; i++) a[i] = sA[(r0 + i) * SA_PITCH + k];
        #pragma unroll
        for (int i = 0; i < 8; i++) {
            acc[i][0] += a[i] * wa.x; acc[i][1] += a[i] * wa.y;
            acc[i][2] += a[i] * wa.z; acc[i][3] += a[i] * wa.w;
            acc[i][4] += a[i] * wb.x; acc[i][5] += a[i] * wb.y;
            acc[i][6] += a[i] * wb.z; acc[i][7] += a[i] * wb.w;
        }
    }
    __syncthreads();

    #pragma unroll
    for (int i = 0; i < 8; i++) {
        #pragma unroll
        for (int j = 0; j < 8; j++) {
            float h = acc[i][j] + sb1[cc + j];
            h = 0.5f * h * (1.0f + erff(h * 0.70710678118654752f));
            sA[(r0 + i) * SA_PITCH + cc + j] = h;
            acc[i][j] = 0.0f;
        }
    }
    __syncthreads();

    #pragma unroll 4
    for (int k = 0; k < 128; k++) {
        float4 wa = *(const float4*)(sW2 + k * 128 + cc);
        float4 wb = *(const float4*)(sW2 + k * 128 + cc + 4);
        float a[8];
        #pragma unroll
        for (int i = 0; i < 8; i++) a[i] = sA[(r0 + i) * SA_PITCH + k];
        #pragma unroll
        for (int i = 0; i < 8; i++) {
            acc[i][0] += a[i] * wa.x; acc[i][1] += a[i] * wa.y;
            acc[i][2] += a[i] * wa.z; acc[i][3] += a[i] * wa.w;
            acc[i][4] += a[i] * wb.x; acc[i][5] += a[i] * wb.y;
            acc[i][6] += a[i] * wb.z; acc[i][7] += a[i] * wb.w;
        }
    }

    #pragma unroll
    for (int i = 0; i < 8; i++) {
        int gr = row0 + r0 + i;
        if (gr < NN) {
            float4 o0 = make_float4(acc[i][0] + sb2[cc],     acc[i][1] + sb2[cc + 1],
                                    acc[i][2] + sb2[cc + 2], acc[i][3] + sb2[cc + 3]);
            float4 o1 = make_float4(acc[i][4] + sb2[cc + 4], acc[i][5] + sb2[cc + 5],
                                    acc[i][6] + sb2[cc + 6], acc[i][7] + sb2[cc + 7]);
            *(float4*)(C + (size_t)gr * DD + cc) = o0;
            *(float4*)(C + (size_t)gr * DD + cc + 4) = o1;
        }
    }
}

// ---------------------------------------------------------------------------
// Launch
// ---------------------------------------------------------------------------
extern "C" void kernel_launch(void* const* d_in, const int* in_sizes, int n_in,
                              void* d_out, int out_size) {
    const float* x         = (const float*)d_in[0];
    const float* edge_attr = (const float*)d_in[1];
    const float* W1        = (const float*)d_in[2];
    const float* b1        = (const float*)d_in[3];
    const float* W2        = (const float*)d_in[4];
    const float* b2        = (const float*)d_in[5];
    const float* We        = (const float*)d_in[6];
    const float* be        = (const float*)d_in[7];
    const float* eps       = (const float*)d_in[8];
    const void*  edge_idx  = d_in[9];
    float* out = (float*)d_out;

    float *bufA, *bufB;
    cudaGetSymbolAddress((void**)&bufA, g_bufA);
    cudaGetSymbolAddress((void**)&bufB, g_bufB);

    cudaFuncSetAttribute(mlp_kernel,
                         cudaFuncAttributeMaxDynamicSharedMemorySize,
                         MLP_SMEM_BYTES);

    // ---- CSR build (once per launch, reused by all 3 layers) ----
    detect_idx_kernel<<<1, 32>>>((const long long*)edge_idx);
    zero_cnt_kernel<<<(NN + 255) / 256, 256>>>();
    hist_kernel<<<(NE + 255) / 256, 256>>>(edge_idx);
    scan_kernel<<<1, 1024>>>();
    scatter_kernel<<<(NE + 255) / 256, 256>>>(edge_idx);

    const int aggr_blocks = (NN * 32 + 255) / 256;  // one warp per node
    const int mlp_blocks  = (NN + 127) / 128;

    const float* xin = x;
    for (int l = 0; l < 3; l++) {
        float* aggr = (l == 1) ? bufB : bufA;
        float* xout = (l == 0) ? bufA : ((l == 1) ? bufB : out);

        aggr_kernel<<<aggr_blocks, 256>>>(xin, edge_attr, We + l * ED * DD,
                                          be + l * DD, eps, l, aggr);
        mlp_kernel<<<mlp_blocks, 256, MLP_SMEM_BYTES>>>(
            aggr, W1 + l * DD * DD, b1 + l * DD,
            W2 + l * DD * DD, b2 + l * DD, xout);
        xin = xout;
    }
}